// round 17
// baseline (speedup 1.0000x reference)
#include <cuda_runtime.h>

#define DM   2048     // d_model
#define DL   512      // d_latent
#define NH   16
#define HD   128
#define SEQ  2048
#define NB   2
#define TOK  (NB*SEQ) // 4096

typedef unsigned int uint32;

// ---- tf32 mma helpers (layout verified in R6) ----
__device__ __forceinline__ uint32 f2tf32(float f) {
    uint32 u;
    asm("cvt.rna.tf32.f32 %0, %1;" : "=r"(u) : "f"(f));
    return u;
}
__device__ __forceinline__ float f2tf32f(float f) {
    return __uint_as_float(f2tf32(f));
}
__device__ __forceinline__ void mma_tf32(float* d, const uint32* a, const uint32* b) {
    asm volatile(
        "mma.sync.aligned.m16n8k8.row.col.f32.tf32.tf32.f32 "
        "{%0,%1,%2,%3}, {%4,%5,%6,%7}, {%8,%9}, {%0,%1,%2,%3};"
        : "+f"(d[0]), "+f"(d[1]), "+f"(d[2]), "+f"(d[3])
        : "r"(a[0]), "r"(a[1]), "r"(a[2]), "r"(a[3]), "r"(b[0]), "r"(b[1]));
}

// Scratch (allocation-free rule: __device__ globals, device-code refs only)
__device__ float g_q  [TOK*DM];
__device__ float g_ckv[TOK*DL];
__device__ float g_k  [TOK*DM];
__device__ float g_v  [TOK*DM];
__device__ float g_ctx[TOK*DM];

// ---------------------------------------------------------------------------
// C[M,N] = A[M,K] @ B[N,K]^T  (+ optional bias[N]) via tf32 mma.
// EXACT R13/R16 GEMM (proven): BK=32, 256 threads, single-buffer static smem,
// GP=36, scalar LDS.32 fragment loads.
// ---------------------------------------------------------------------------
#define GP 36   // smem pitch (floats)

template<int MODE, int MTILES>
__global__ __launch_bounds__(256) void tgemm_nt(
    const float* __restrict__ Aarg, const float* __restrict__ B,
    const float* __restrict__ bias, float* __restrict__ Carg,
    int M, int N, int K)
{
    const float* A;
    const float* Bp;
    float* C;
    int bx = blockIdx.x;
    if      (MODE == 0)  { A = Aarg;  C = g_ckv; Bp = B; }
    else if (MODE == 1)  { A = Aarg;  C = g_q;   Bp = B; }
    else if (MODE == 23) {
        A = g_ckv;
        const bool isV = bx >= (DM / 128);
        bx &= (DM / 128) - 1;
        C  = isV ? g_v : g_k;
        Bp = isV ? bias : B;   // bias arg carries W_uv in this mode
    }
    else                 { A = g_ctx; C = Carg;  Bp = B; }

    constexpr int MROWS = 64 * MTILES;
    __shared__ float As[MROWS][GP];
    __shared__ float Bs[128][GP];

    const int tid  = threadIdx.x;
    const int lane = tid & 31;
    const int w    = tid >> 5;
    const int g    = lane >> 2;
    const int t    = lane & 3;
    const int wm   = w & 3;
    const int wn   = w >> 2;
    const int row0 = blockIdx.y * MROWS;
    const int col0 = bx * 128;

    constexpr int TPR_A = 256 / MROWS;
    constexpr int KPT_A = 32 / TPR_A;
    constexpr int NV_A  = KPT_A / 4;
    const int alr  = tid / TPR_A;
    const int alko = (tid % TPR_A) * KPT_A;
    const int blr  = tid >> 1;
    const int blko = (tid & 1) * 16;

    float acc[MTILES][8][4];
#pragma unroll
    for (int mt = 0; mt < MTILES; mt++)
#pragma unroll
        for (int nt = 0; nt < 8; nt++)
#pragma unroll
            for (int r = 0; r < 4; r++) acc[mt][nt][r] = 0.f;

    float4 pa[NV_A], pb[4];
#pragma unroll
    for (int i = 0; i < NV_A; i++)
        pa[i] = *(const float4*)(A + (size_t)(row0 + alr) * K + alko + i * 4);
#pragma unroll
    for (int i = 0; i < 4; i++)
        pb[i] = *(const float4*)(Bp + (size_t)(col0 + blr) * K + blko + i * 4);

    for (int k0 = 0; k0 < K; k0 += 32) {
        __syncthreads();
#pragma unroll
        for (int i = 0; i < NV_A; i++) {
            float4 va = pa[i];
            float4 ca;
            ca.x = f2tf32f(va.x); ca.y = f2tf32f(va.y);
            ca.z = f2tf32f(va.z); ca.w = f2tf32f(va.w);
            *(float4*)&As[alr][alko + i * 4] = ca;
        }
#pragma unroll
        for (int i = 0; i < 4; i++) {
            float4 vb = pb[i];
            float4 cb;
            cb.x = f2tf32f(vb.x); cb.y = f2tf32f(vb.y);
            cb.z = f2tf32f(vb.z); cb.w = f2tf32f(vb.w);
            *(float4*)&Bs[blr][blko + i * 4] = cb;
        }
        __syncthreads();

        if (k0 + 32 < K) {
#pragma unroll
            for (int i = 0; i < NV_A; i++)
                pa[i] = *(const float4*)(A + (size_t)(row0 + alr) * K + k0 + 32 + alko + i * 4);
#pragma unroll
            for (int i = 0; i < 4; i++)
                pb[i] = *(const float4*)(Bp + (size_t)(col0 + blr) * K + k0 + 32 + blko + i * 4);
        }

#pragma unroll
        for (int s = 0; s < 4; s++) {
            const int kb = s * 8 + t;
            uint32 af[MTILES][4], bf[8][2];
#pragma unroll
            for (int mt = 0; mt < MTILES; mt++) {
                const int rb = wm * (16 * MTILES) + mt * 16;
                af[mt][0] = __float_as_uint(As[rb + g    ][kb]);
                af[mt][1] = __float_as_uint(As[rb + 8 + g][kb]);
                af[mt][2] = __float_as_uint(As[rb + g    ][kb + 4]);
                af[mt][3] = __float_as_uint(As[rb + 8 + g][kb + 4]);
            }
#pragma unroll
            for (int nt = 0; nt < 8; nt++) {
                const int nb = wn * 64 + nt * 8 + g;
                bf[nt][0] = __float_as_uint(Bs[nb][kb]);
                bf[nt][1] = __float_as_uint(Bs[nb][kb + 4]);
            }
#pragma unroll
            for (int mt = 0; mt < MTILES; mt++)
#pragma unroll
                for (int nt = 0; nt < 8; nt++)
                    mma_tf32(acc[mt][nt], af[mt], bf[nt]);
        }
    }

#pragma unroll
    for (int mt = 0; mt < MTILES; mt++) {
        const int ra = row0 + wm * (16 * MTILES) + mt * 16 + g;
#pragma unroll
        for (int nt = 0; nt < 8; nt++) {
            const int cb = col0 + wn * 64 + nt * 8 + 2 * t;
            float b0 = 0.f, b1 = 0.f;
            if (MODE == 4) { b0 = bias[cb]; b1 = bias[cb + 1]; }
            float2 v0 = make_float2(acc[mt][nt][0] + b0, acc[mt][nt][1] + b1);
            float2 v1 = make_float2(acc[mt][nt][2] + b0, acc[mt][nt][3] + b1);
            *(float2*)(C + (size_t)ra * N + cb)       = v0;
            *(float2*)(C + (size_t)(ra + 8) * N + cb) = v1;
        }
    }
}

// ---------------------------------------------------------------------------
// Flash attention via tf32 mma (R16 structure) with PAIRED-K Q/K layout:
// element k of each 8-block stored at col s*8 + 2*(k&3) + ((k>>2)&1), so the
// fragment pair (k, k+4) is ADJACENT -> one LDS.64 per row-half per s-step.
// S-phase fragment issues: 20 -> 10 per s-step. Pitches 136 (row term 8g mod
// 32) -> each 16-lane LDS.64 phase covers 16 distinct even bank-pairs.
// Store side uses per-lane-group rotation to avoid STS conflicts.
// K/V register prefetch and exact masked-tile skip retained from R16.
// ---------------------------------------------------------------------------
#define AQ_P 136
#define AK_P 136
#define AV_P 136
#define AP_P 68
#define SM_AQ 0
#define SM_AK (SM_AQ + 128*AQ_P)      // 17408
#define SM_AV (SM_AK + 64*AK_P)       // 26112
#define SM_AP (SM_AV + 64*AV_P)       // 34816
#define ATTN_FLOATS (SM_AP + 128*AP_P) // 43520
#define ATTN_SMEM_BYTES (ATTN_FLOATS * 4)  // 174080

__global__ __launch_bounds__(256, 1) void attn_mma()
{
    extern __shared__ float sm[];
    float* Qs = sm + SM_AQ;
    float* Ks = sm + SM_AK;
    float* Vs = sm + SM_AV;
    float* Ps = sm + SM_AP;

    const int tid  = threadIdx.x;
    const int lane = tid & 31;
    const int w    = tid >> 5;
    const int g    = lane >> 2;
    const int t    = lane & 3;
    const int bx   = gridDim.x - 1 - blockIdx.x;
    const int bh   = blockIdx.y;
    const int b    = bh >> 4;
    const int h    = bh & 15;
    const int q0   = bx * 128;
    const int r0   = w * 16;

    const float scale = 0.08838834764831845f;

    // K/V loader mapping
    const int krow = tid >> 2;
    const int kcb  = (tid & 3) * 32;
    const float* kbase = g_k + (size_t)(b*SEQ + krow) * DM + h*HD + kcb;
    const float* vbase = g_v + (size_t)(b*SEQ + krow) * DM + h*HD + kcb;

    // ---- load Q (scaled + tf32) into paired-k layout ----
    {
        int row = tid >> 1;
        int cb  = (tid & 1) * 64;
        const float* src = g_q + (size_t)(b*SEQ + q0 + row) * DM + h*HD + cb;
        float* dst = Qs + row * AQ_P + cb;
#pragma unroll
        for (int u = 0; u < 8; u++) {          // 8 k-blocks of 8
            float4 va = *(const float4*)(src + u * 8);
            float4 vb = *(const float4*)(src + u * 8 + 4);
            const float av[4] = {va.x, va.y, va.z, va.w};
            const float bv[4] = {vb.x, vb.y, vb.z, vb.w};
#pragma unroll
            for (int mm = 0; mm < 4; mm++) {
                const int m = (mm + ((tid & 1) << 1)) & 3;   // store stagger
                float2 wv;
                wv.x = f2tf32f(av[m] * scale);   // k = u*8+m   -> even slot
                wv.y = f2tf32f(bv[m] * scale);   // k = u*8+4+m -> odd slot
                *(float2*)(dst + u * 8 + 2 * m) = wv;
            }
        }
    }

    float oacc[16][4];
#pragma unroll
    for (int nt = 0; nt < 16; nt++)
#pragma unroll
        for (int r = 0; r < 4; r++) oacc[nt][r] = 0.f;
    float mA = -1e30f, mB = -1e30f, lA = 0.f, lB = 0.f;

    const int nkt = (q0 + 128) / 64;

    // ---- prefetch tile 0 K/V into registers ----
    float4 pk[8], pv[8];
#pragma unroll
    for (int i = 0; i < 8; i++) {
        pk[i] = *(const float4*)(kbase + i * 4);
        pv[i] = *(const float4*)(vbase + i * 4);
    }

    for (int kt = 0; kt < nkt; kt++) {
        const int k0 = kt * 64;
        __syncthreads();   // all warps done with prior Ks/Vs (and Q stores, iter 0)

        // ---- convert + store prefetched K (paired) and V (natural) ----
        {
            float* kdst = Ks + krow * AK_P + kcb;
            float* vdst = Vs + krow * AV_P + kcb;
#pragma unroll
            for (int uu = 0; uu < 4; uu++) {    // 4 k-blocks of 8
                const int u = (uu + (tid & 3)) & 3;   // store stagger
                float4 va = pk[2*u], vb = pk[2*u+1];
                const float av[4] = {va.x, va.y, va.z, va.w};
                const float bv[4] = {vb.x, vb.y, vb.z, vb.w};
#pragma unroll
                for (int m = 0; m < 4; m++) {
                    float2 wv;
                    wv.x = f2tf32f(av[m]);
                    wv.y = f2tf32f(bv[m]);
                    *(float2*)(kdst + u * 8 + 2 * m) = wv;
                }
            }
#pragma unroll
            for (int i = 0; i < 8; i++) {
                float4 vv = pv[i];
                vdst[i*4+0] = f2tf32f(vv.x);
                vdst[i*4+1] = f2tf32f(vv.y);
                vdst[i*4+2] = f2tf32f(vv.z);
                vdst[i*4+3] = f2tf32f(vv.w);
            }
        }
        __syncthreads();

        // ---- issue next tile's loads (hidden under compute below) ----
        if (kt + 1 < nkt) {
            const size_t off = (size_t)(k0 + 64) * DM;
#pragma unroll
            for (int i = 0; i < 8; i++) {
                pk[i] = *(const float4*)(kbase + off + i * 4);
                pv[i] = *(const float4*)(vbase + off + i * 4);
            }
        }

        // Tile entirely above this warp's diagonal -> exact no-op, skip compute.
        if (k0 > q0 + r0 + 15) continue;

        // ---- S = Q @ K^T (paired LDS.64 fragment loads) ----
        float sacc[8][4];
#pragma unroll
        for (int nt = 0; nt < 8; nt++)
#pragma unroll
            for (int r = 0; r < 4; r++) sacc[nt][r] = 0.f;

#pragma unroll
        for (int s = 0; s < 16; s++) {
            const int sb = s * 8;
            uint32 af[4];
            float2 qa = *(const float2*)(Qs + (r0 + g    ) * AQ_P + sb + 2*t);
            float2 qb = *(const float2*)(Qs + (r0 + 8 + g) * AQ_P + sb + 2*t);
            af[0] = __float_as_uint(qa.x);   // Q[g][kb]
            af[2] = __float_as_uint(qa.y);   // Q[g][kb+4]
            af[1] = __float_as_uint(qb.x);   // Q[g+8][kb]
            af[3] = __float_as_uint(qb.y);   // Q[g+8][kb+4]
#pragma unroll
            for (int nt = 0; nt < 8; nt++) {
                float2 kk = *(const float2*)(Ks + (nt*8 + g) * AK_P + sb + 2*t);
                uint32 bf[2];
                bf[0] = __float_as_uint(kk.x);
                bf[1] = __float_as_uint(kk.y);
                mma_tf32(sacc[nt], af, bf);
            }
        }

        if (k0 + 63 > q0 + r0) {
            const int rowA = q0 + r0 + g;
            const int rowB = rowA + 8;
#pragma unroll
            for (int nt = 0; nt < 8; nt++) {
                const int col = k0 + nt*8 + 2*t;
                if (col     > rowA) sacc[nt][0] = -1e30f;
                if (col + 1 > rowA) sacc[nt][1] = -1e30f;
                if (col     > rowB) sacc[nt][2] = -1e30f;
                if (col + 1 > rowB) sacc[nt][3] = -1e30f;
            }
        }

        // ---- online softmax (quad reduction) ----
        float mxA = -1e30f, mxB = -1e30f;
#pragma unroll
        for (int nt = 0; nt < 8; nt++) {
            mxA = fmaxf(mxA, fmaxf(sacc[nt][0], sacc[nt][1]));
            mxB = fmaxf(mxB, fmaxf(sacc[nt][2], sacc[nt][3]));
        }
        mxA = fmaxf(mxA, __shfl_xor_sync(0xffffffffu, mxA, 1));
        mxA = fmaxf(mxA, __shfl_xor_sync(0xffffffffu, mxA, 2));
        mxB = fmaxf(mxB, __shfl_xor_sync(0xffffffffu, mxB, 1));
        mxB = fmaxf(mxB, __shfl_xor_sync(0xffffffffu, mxB, 2));

        const float mnA = fmaxf(mA, mxA);
        const float mnB = fmaxf(mB, mxB);
        const float corrA = __expf(mA - mnA);
        const float corrB = __expf(mB - mnB);

        float sumA = 0.f, sumB = 0.f;
        __syncwarp();
#pragma unroll
        for (int nt = 0; nt < 8; nt++) {
            float pA0 = __expf(sacc[nt][0] - mnA);
            float pA1 = __expf(sacc[nt][1] - mnA);
            float pB0 = __expf(sacc[nt][2] - mnB);
            float pB1 = __expf(sacc[nt][3] - mnB);
            sumA += pA0 + pA1;
            sumB += pB0 + pB1;
            float2 wa = make_float2(f2tf32f(pA0), f2tf32f(pA1));
            float2 wb = make_float2(f2tf32f(pB0), f2tf32f(pB1));
            *(float2*)(Ps + (r0 + g    ) * AP_P + nt*8 + 2*t) = wa;
            *(float2*)(Ps + (r0 + 8 + g) * AP_P + nt*8 + 2*t) = wb;
        }
        sumA += __shfl_xor_sync(0xffffffffu, sumA, 1);
        sumA += __shfl_xor_sync(0xffffffffu, sumA, 2);
        sumB += __shfl_xor_sync(0xffffffffu, sumB, 1);
        sumB += __shfl_xor_sync(0xffffffffu, sumB, 2);

        lA = lA * corrA + sumA;
        lB = lB * corrB + sumB;
        mA = mnA;
        mB = mnB;

#pragma unroll
        for (int nt = 0; nt < 16; nt++) {
            oacc[nt][0] *= corrA; oacc[nt][1] *= corrA;
            oacc[nt][2] *= corrB; oacc[nt][3] *= corrB;
        }
        __syncwarp();

        // ---- O += P @ V (unchanged scalar fragment loads) ----
#pragma unroll
        for (int s = 0; s < 8; s++) {
            const int kb = s * 8 + t;
            uint32 af[4];
            af[0] = __float_as_uint(Ps[(r0 + g    ) * AP_P + kb]);
            af[1] = __float_as_uint(Ps[(r0 + 8 + g) * AP_P + kb]);
            af[2] = __float_as_uint(Ps[(r0 + g    ) * AP_P + kb + 4]);
            af[3] = __float_as_uint(Ps[(r0 + 8 + g) * AP_P + kb + 4]);
#pragma unroll
            for (int nt = 0; nt < 16; nt++) {
                uint32 bf[2];
                bf[0] = __float_as_uint(Vs[(kb    ) * AV_P + nt*8 + g]);
                bf[1] = __float_as_uint(Vs[(kb + 4) * AV_P + nt*8 + g]);
                mma_tf32(oacc[nt], af, bf);
            }
        }
    }

    const float invA = 1.f / lA;
    const float invB = 1.f / lB;
    float* baseA = g_ctx + (size_t)(b*SEQ + q0 + r0 + g    ) * DM + h*HD;
    float* baseB = g_ctx + (size_t)(b*SEQ + q0 + r0 + 8 + g) * DM + h*HD;
#pragma unroll
    for (int nt = 0; nt < 16; nt++) {
        *(float2*)(baseA + nt*8 + 2*t) = make_float2(oacc[nt][0]*invA, oacc[nt][1]*invA);
        *(float2*)(baseB + nt*8 + 2*t) = make_float2(oacc[nt][2]*invB, oacc[nt][3]*invB);
    }
}

// ---------------------------------------------------------------------------
// Launch: strictly serial, stateless, static-smem GEMMs.
// ---------------------------------------------------------------------------
extern "C" void kernel_launch(void* const* d_in, const int* in_sizes, int n_in,
                              void* d_out, int out_size)
{
    (void)in_sizes; (void)n_in; (void)out_size;
    const float* x    = (const float*)d_in[0];
    const float* W_q  = (const float*)d_in[1];
    const float* W_dkv= (const float*)d_in[2];
    const float* W_uk = (const float*)d_in[3];
    const float* W_uv = (const float*)d_in[4];
    const float* W_o  = (const float*)d_in[5];
    const float* W_b  = (const float*)d_in[6];
    float* out = (float*)d_out;

    cudaFuncSetAttribute(attn_mma,
                         cudaFuncAttributeMaxDynamicSharedMemorySize,
                         ATTN_SMEM_BYTES);

    dim3 blk(256);
    tgemm_nt<0, 1><<<dim3(DL/128, TOK/64), blk>>>(x, W_dkv, nullptr, nullptr, TOK, DL, DM);
    tgemm_nt<1, 2><<<dim3(DM/128, TOK/128), blk>>>(x, W_q, nullptr, nullptr, TOK, DM, DM);
    tgemm_nt<23, 2><<<dim3(2*DM/128, TOK/128), blk>>>(nullptr, W_uk, W_uv, nullptr, TOK, DM, DL);
    attn_mma<<<dim3(SEQ/128, NB*NH), dim3(256), ATTN_SMEM_BYTES>>>();
    tgemm_nt<4, 2><<<dim3(DM/128, TOK/128), blk>>>(nullptr, W_o, W_b, out, TOK, DM, DM);
}